// round 17
// baseline (speedup 1.0000x reference)
#include <cuda_runtime.h>

// Shapes (fixed by the problem)
#define B_   8
#define C_   256
#define MID_ 16
#define H_   128
#define W_   128
#define HW_  (H_*W_)      // 16384
#define PADK 3

// Scratch (no allocs allowed)
__device__ float g_xlow0[B_*MID_*HW_];   // 8 MB : partial sum c=0..127
__device__ float g_xlow1[B_*MID_*HW_];   // 8 MB : partial sum c=128..255
__device__ float g_wh[B_*HW_];           // 0.5 MB : cos^2(angle)

// ---- packed f32x2 helpers (sm_103a) ----
static __device__ __forceinline__ unsigned long long pack2(float lo, float hi) {
    unsigned long long r;
    asm("mov.b64 %0, {%1, %2};" : "=l"(r) : "f"(lo), "f"(hi));
    return r;
}
static __device__ __forceinline__ void unpack2(unsigned long long v, float& lo, float& hi) {
    asm("mov.b64 {%0, %1}, %2;" : "=f"(lo), "=f"(hi) : "l"(v));
}
static __device__ __forceinline__ unsigned long long ffma2(
    unsigned long long a, unsigned long long b, unsigned long long c) {
    unsigned long long d;
    asm("fma.rn.f32x2 %0, %1, %2, %3;" : "=l"(d) : "l"(a), "l"(b), "l"(c));
    return d;
}

// ---------------------------------------------------------------------------
// K1 (R8 exact — best measured reduce, 30.9us): partial x_low over a
// 128-channel half.  2 px/thread, 8-deep LDG.64 batch, 128-thread blocks.
// grid (512, 2): x = pixel pairs, y = c-half.
// ---------------------------------------------------------------------------
__global__ __launch_bounds__(128) void k_reduce(const float* __restrict__ x,
                                                const float* __restrict__ angle,
                                                const float* __restrict__ wr) {
    __shared__ unsigned long long s_w[128*8];   // 8 KB (this c-half)
    int tid   = threadIdx.x;
    int cz    = blockIdx.y;                     // 0 or 1
    int cbase = cz * 128;

    // pack weights for this half: thread t owns channel cbase+t
    {
        int c = cbase + tid;
        float wv[16];
        #pragma unroll
        for (int m = 0; m < 16; m++) wv[m] = wr[m * C_ + c];
        #pragma unroll
        for (int q = 0; q < 8; q++)
            s_w[tid * 8 + q] = pack2(wv[2*q], wv[2*q+1]);
    }
    __syncthreads();

    int t  = blockIdx.x * 128 + tid;     // 0..65535
    int pp = t * 2;                      // pixel pair base
    int b  = pp >> 14;
    int hw = pp & (HW_ - 1);

    const float* xp = x + (long)b * C_ * HW_ + (long)cbase * HW_ + hw;

    unsigned long long aA[8], aB[8];
    #pragma unroll
    for (int q = 0; q < 8; q++) { aA[q]=0ULL; aB[q]=0ULL; }

    #pragma unroll
    for (int c0 = 0; c0 < 128; c0 += 8) {
        float2 vv[8];
        #pragma unroll
        for (int u = 0; u < 8; u++)
            vv[u] = __ldcs(reinterpret_cast<const float2*>(xp + (long)(c0 + u) * HW_));
        #pragma unroll
        for (int u = 0; u < 8; u++) {
            unsigned long long vA = pack2(vv[u].x, vv[u].x);
            unsigned long long vB = pack2(vv[u].y, vv[u].y);
            const ulonglong2* wrow =
                reinterpret_cast<const ulonglong2*>(&s_w[(c0 + u) * 8]);
            ulonglong2 w01 = wrow[0];
            ulonglong2 w23 = wrow[1];
            ulonglong2 w45 = wrow[2];
            ulonglong2 w67 = wrow[3];
            aA[0]=ffma2(vA,w01.x,aA[0]); aB[0]=ffma2(vB,w01.x,aB[0]);
            aA[1]=ffma2(vA,w01.y,aA[1]); aB[1]=ffma2(vB,w01.y,aB[1]);
            aA[2]=ffma2(vA,w23.x,aA[2]); aB[2]=ffma2(vB,w23.x,aB[2]);
            aA[3]=ffma2(vA,w23.y,aA[3]); aB[3]=ffma2(vB,w23.y,aB[3]);
            aA[4]=ffma2(vA,w45.x,aA[4]); aB[4]=ffma2(vB,w45.x,aB[4]);
            aA[5]=ffma2(vA,w45.y,aA[5]); aB[5]=ffma2(vB,w45.y,aB[5]);
            aA[6]=ffma2(vA,w67.x,aA[6]); aB[6]=ffma2(vB,w67.x,aB[6]);
            aA[7]=ffma2(vA,w67.y,aA[7]); aB[7]=ffma2(vB,w67.y,aB[7]);
        }
    }

    float* op = (cz ? g_xlow1 : g_xlow0) + (long)b * MID_ * HW_ + hw;
    #pragma unroll
    for (int q = 0; q < 8; q++) {
        float A0,A1,B0,B1;
        unpack2(aA[q], A0, A1);
        unpack2(aB[q], B0, B1);
        *reinterpret_cast<float2*>(op + (long)(2*q)   * HW_) = make_float2(A0,B0);
        *reinterpret_cast<float2*>(op + (long)(2*q+1) * HW_) = make_float2(A1,B1);
    }

    if (cz == 0) {
        float2 a2 = *reinterpret_cast<const float2*>(angle + b * HW_ + hw);
        float c0v = cosf(a2.x), c1v = cosf(a2.y);
        *reinterpret_cast<float2*>(g_wh + pp) = make_float2(c0v*c0v, c1v*c1v);
    }
}

// ---------------------------------------------------------------------------
// K2: FUSED conv + expand.  One block = one 32x8 spatial tile of one batch.
// Phase 1: separable dynamic conv for all 16 m -> ol[16][256] in smem.
// Phase 2: expand 256 px x 256 c straight from smem (no outlow round trip).
// grid (4, 16, 8) = 512 blocks, 256 threads.
// ---------------------------------------------------------------------------
#define TW 32
#define TH 8
#define HH (TH + 6)      // 14
#define HW2 (TW + 6)     // 38

// f(a)=exp(-a^2/12.5), g(a)=exp(-a^2/2), a=-3..3
#define F0 0.48675225595997157f
#define F1 0.7261490370736909f
#define F2 0.9231163463866358f
#define F3 1.0f
#define G0 0.011108996538242306f
#define G1 0.1353352832366127f
#define G2 0.6065306597126334f
#define G3 1.0f
#define SUMF (F3 + 2.0f*(F0 + F1 + F2))
#define SUMG (G3 + 2.0f*(G0 + G1 + G2))
#define INVS (1.0f/(SUMF*SUMG + 1e-8f))

__global__ __launch_bounds__(256) void k_fused(float* __restrict__ out,
                                               const float* __restrict__ we) {
    __shared__ float  s_t[HH * HW2];                 // 2.2 KB halo tile
    __shared__ float2 s_hf[HH * TW];                 // 3.5 KB (Hg,Hf)
    __shared__ __align__(16) float s_ol[MID_][TW*TH];// 16 KB out_low tile
    __shared__ unsigned long long s_we[C_*8];        // 16 KB packed weights

    const float Fk[7] = {F0, F1, F2, F3, F2, F1, F0};
    const float Gk[7] = {G0, G1, G2, G3, G2, G1, G0};

    int tid = threadIdx.x;
    int b   = blockIdx.z;
    int h0  = blockIdx.y * TH;
    int w0  = blockIdx.x * TW;

    // load all packed expand weights (u64 reinterpret of row-major we)
    {
        const unsigned long long* we64 =
            reinterpret_cast<const unsigned long long*>(we);
        #pragma unroll
        for (int i = tid; i < C_*8; i += 256) s_we[i] = we64[i];
    }

    // this thread's conv pixel (1:1, 256 px)
    int py = tid >> 5;           // 0..7
    int wx = tid & 31;           // 0..31
    float wh = g_wh[b * HW_ + (h0 + py) * W_ + (w0 + wx)];

    // ---------------- Phase 1: conv for each m ----------------
    for (int m = 0; m < MID_; m++) {
        long bz = (long)(b * MID_ + m) * HW_;
        const float* xl0 = g_xlow0 + bz;
        const float* xl1 = g_xlow1 + bz;

        __syncthreads();   // protect s_t / s_hf from previous iteration readers
        for (int idx = tid; idx < HH * HW2; idx += 256) {
            int hh = idx / HW2, ww = idx - hh * HW2;
            int gh = h0 + hh - PADK;
            int gw = w0 + ww - PADK;
            gh = gh < 0 ? -gh : (gh > H_-1 ? 2*(H_-1) - gh : gh);
            gw = gw < 0 ? -gw : (gw > W_-1 ? 2*(W_-1) - gw : gw);
            int o = gh * W_ + gw;
            s_t[idx] = xl0[o] + xl1[o];
        }
        __syncthreads();

        // stage 1: horizontal 1-D passes, 14x32 = 448 jobs
        for (int idx = tid; idx < HH * TW; idx += 256) {
            int r = idx >> 5;
            int xw = idx & 31;
            const float* row = s_t + r * HW2 + xw;
            float hg = 0.f, hf = 0.f;
            #pragma unroll
            for (int j = 0; j < 7; j++) {
                float v = row[j];
                hg = fmaf(v, Gk[j], hg);
                hf = fmaf(v, Fk[j], hf);
            }
            s_hf[idx] = make_float2(hg, hf);
        }
        __syncthreads();

        // stage 2: vertical 1-D passes, 1 px per thread
        float aH = 0.f, aV = 0.f;
        #pragma unroll
        for (int i = 0; i < 7; i++) {
            float2 hv = s_hf[(py + i) * TW + wx];
            aH = fmaf(hv.x, Fk[i] * INVS, aH);
            aV = fmaf(hv.y, Gk[i] * INVS, aV);
        }
        s_ol[m][tid] = wh * aH + (1.f - wh) * aV;
    }
    __syncthreads();

    // ---------------- Phase 2: expand from smem ----------------
    // 64 px-threads (4 px each) x 4 c-groups (64 c each)
    int cg = tid >> 6;            // 0..3
    int pt = tid & 63;            // 0..63
    int p0 = pt * 4;              // pixel quad within tile (row-aligned)
    int cbase = cg * 64;

    // ol quads for this thread's 4 pixels, packed as m-pairs
    unsigned long long olA[8], olB[8], olC[8], olD[8];
    #pragma unroll
    for (int q = 0; q < 8; q++) {
        float4 e = *reinterpret_cast<const float4*>(&s_ol[2*q  ][p0]);
        float4 o = *reinterpret_cast<const float4*>(&s_ol[2*q+1][p0]);
        olA[q] = pack2(e.x, o.x);
        olB[q] = pack2(e.y, o.y);
        olC[q] = pack2(e.z, o.z);
        olD[q] = pack2(e.w, o.w);
    }

    int eh = h0 + (p0 >> 5);      // output row
    int ew = w0 + (p0 & 31);      // output col (quad start)
    float* op = out + ((long)b * C_ + cbase) * HW_ + eh * W_ + ew;

    #pragma unroll 2
    for (int c = 0; c < 64; c++) {
        const ulonglong2* wrow =
            reinterpret_cast<const ulonglong2*>(&s_we[(cbase + c) * 8]);
        ulonglong2 w01 = wrow[0];
        ulonglong2 w23 = wrow[1];
        ulonglong2 w45 = wrow[2];
        ulonglong2 w67 = wrow[3];
        unsigned long long a0=0ULL, a1=0ULL, a2=0ULL, a3=0ULL;
        a0=ffma2(olA[0],w01.x,a0); a1=ffma2(olB[0],w01.x,a1); a2=ffma2(olC[0],w01.x,a2); a3=ffma2(olD[0],w01.x,a3);
        a0=ffma2(olA[1],w01.y,a0); a1=ffma2(olB[1],w01.y,a1); a2=ffma2(olC[1],w01.y,a2); a3=ffma2(olD[1],w01.y,a3);
        a0=ffma2(olA[2],w23.x,a0); a1=ffma2(olB[2],w23.x,a1); a2=ffma2(olC[2],w23.x,a2); a3=ffma2(olD[2],w23.x,a3);
        a0=ffma2(olA[3],w23.y,a0); a1=ffma2(olB[3],w23.y,a1); a2=ffma2(olC[3],w23.y,a2); a3=ffma2(olD[3],w23.y,a3);
        a0=ffma2(olA[4],w45.x,a0); a1=ffma2(olB[4],w45.x,a1); a2=ffma2(olC[4],w45.x,a2); a3=ffma2(olD[4],w45.x,a3);
        a0=ffma2(olA[5],w45.y,a0); a1=ffma2(olB[5],w45.y,a1); a2=ffma2(olC[5],w45.y,a2); a3=ffma2(olD[5],w45.y,a3);
        a0=ffma2(olA[6],w67.x,a0); a1=ffma2(olB[6],w67.x,a1); a2=ffma2(olC[6],w67.x,a2); a3=ffma2(olD[6],w67.x,a3);
        a0=ffma2(olA[7],w67.y,a0); a1=ffma2(olB[7],w67.y,a1); a2=ffma2(olC[7],w67.y,a2); a3=ffma2(olD[7],w67.y,a3);
        float l0,h0v,l1,h1v,l2,h2v,l3,h3v;
        unpack2(a0, l0, h0v);
        unpack2(a1, l1, h1v);
        unpack2(a2, l2, h2v);
        unpack2(a3, l3, h3v);
        float4 r = make_float4(l0+h0v, l1+h1v, l2+h2v, l3+h3v);
        __stcs(reinterpret_cast<float4*>(op + (long)c * HW_), r);
    }
}

// ---------------------------------------------------------------------------
extern "C" void kernel_launch(void* const* d_in, const int* in_sizes, int n_in,
                              void* d_out, int out_size) {
    const float* x      = (const float*)d_in[0];   // (8,256,128,128)
    const float* angle  = (const float*)d_in[1];   // (8,128,128)
    const float* wr     = (const float*)d_in[2];   // (16,256)
    const float* we     = (const float*)d_in[3];   // (256,16)
    float* out          = (float*)d_out;           // (8,256,128,128)

    (void)in_sizes; (void)n_in; (void)out_size;

    dim3 rgrid(512, 2);                            // pixel pairs x c-halves
    k_reduce<<<rgrid, 128>>>(x, angle, wr);        // 1024 blocks

    dim3 fgrid(W_/TW, H_/TH, B_);                  // (4, 16, 8) = 512 blocks
    k_fused<<<fgrid, 256>>>(out, we);
}